// round 13
// baseline (speedup 1.0000x reference)
#include <cuda_runtime.h>
#include <math.h>
#include <stdint.h>

// Problem constants
#define B_   4
#define N_   8400
#define NM_  32
#define H_   160
#define W_   160
#define D_   100
#define HW_  (H_*W_)          // 25600
#define OW_  640
#define OH_  640

// Scratch: sigmoid masks [B][D][H][W] fp32 = 40.96 MB
__device__ float g_S[(size_t)B_ * D_ * HW_];

// Packed fp32x2 FMA (Blackwell FFMA2) — PTX-only
__device__ __forceinline__ float2 ffma2(float2 a, float2 b, float2 c) {
    union { float2 f; unsigned long long u; } ua, ub, uc, ur;
    ua.f = a; ub.f = b; uc.f = c;
    asm("fma.rn.f32x2 %0, %1, %2, %3;" : "=l"(ur.u) : "l"(ua.u), "l"(ub.u), "l"(uc.u));
    return ur.f;
}

// ---------------------------------------------------------------------------
// Kernel A: coeff gather + GEMM over NM=32 + sigmoid -> g_S.
// Launched per 25-d chunk: grid (25, 5, 4); block 256.
// Thread: 4 adjacent px x 5 d via FFMA2 (low regs -> high occupancy).
// ---------------------------------------------------------------------------
#define DT_  5
#define PXT_ 4

__global__ void __launch_bounds__(256)
kernelA(const float* __restrict__ mc,
        const float* __restrict__ proto,
        const void* __restrict__ det,      // int32 vs int64 detected on device
        const int dBase)
{
    const int b  = blockIdx.z;
    const int d0 = dBase + blockIdx.y * DT_;
    const int p0 = blockIdx.x * (256 * PXT_) + threadIdx.x * PXT_;

    // int64 det values < 2^31 -> all odd int32 words zero
    const int* d32 = (const int*)det;
    bool is64 = true;
    #pragma unroll
    for (int k = 0; k < 8; k++) if (d32[2 * k + 1] != 0) is64 = false;

    __shared__ float sc[NM_][DT_];
    for (int i = threadIdx.x; i < NM_ * DT_; i += 256) {
        const int n = i / DT_;
        const int d = i % DT_;
        const int flat = b * D_ + d0 + d;
        long long idx = is64 ? ((const long long*)det)[flat] : (long long)d32[flat];
        idx = min(max(idx, 0LL), (long long)(N_ - 1));
        sc[n][d] = mc[((long long)b * N_ + idx) * NM_ + n];
    }
    __syncthreads();

    float2 acc[DT_][2];
    #pragma unroll
    for (int d = 0; d < DT_; d++) {
        acc[d][0] = make_float2(0.f, 0.f);
        acc[d][1] = make_float2(0.f, 0.f);
    }

    const float* pbase = proto + (size_t)b * NM_ * HW_ + p0;

    #pragma unroll 8
    for (int n = 0; n < NM_; n++) {
        const float4 p = *reinterpret_cast<const float4*>(pbase + (size_t)n * HW_);
        const float2 pa = make_float2(p.x, p.y);
        const float2 pb = make_float2(p.z, p.w);
        #pragma unroll
        for (int d = 0; d < DT_; d++) {
            const float c = sc[n][d];
            const float2 cc = make_float2(c, c);
            acc[d][0] = ffma2(pa, cc, acc[d][0]);
            acc[d][1] = ffma2(pb, cc, acc[d][1]);
        }
    }

    #pragma unroll
    for (int d = 0; d < DT_; d++) {
        float4 s;
        s.x = 1.0f / (1.0f + expf(-acc[d][0].x));
        s.y = 1.0f / (1.0f + expf(-acc[d][0].y));
        s.z = 1.0f / (1.0f + expf(-acc[d][1].x));
        s.w = 1.0f / (1.0f + expf(-acc[d][1].y));
        *reinterpret_cast<float4*>(g_S + ((size_t)(b * D_ + d0 + d)) * HW_ + p0) = s;
    }
}

// ---------------------------------------------------------------------------
// Kernel B (R9 design, unchanged): 4x bilinear upsample + threshold; per-warp
// row pipelines with per-row TMA bulk stores (double-buffered, wait read 1).
// Launched per 25-d chunk: grid (8 bands, 25 d, 4 b); block 256 (8 warps);
// smem 55.0 KB -> 4 CTAs/SM. Warp w: rows Y0 + w + 8*ri, ri 0..9.
// ---------------------------------------------------------------------------
#define SRCROWS      22                                  // 20 + 2 halo
#define BAND_FLOATS  (SRCROWS * 160)                     // 3520 floats
#define ROW_FLOATS   OW_                                 // 640 floats = 2560 B
#define SMEMB_BYTES  ((BAND_FLOATS + 8 * 2 * ROW_FLOATS) * 4)   // 55040 B

__global__ void __launch_bounds__(256)
kernelB(float* __restrict__ out, const int dBase)
{
    extern __shared__ float smem[];
    float* sS = smem;                                    // [22][160] band

    const int band = blockIdx.x;                         // 0..7
    const int d    = dBase + blockIdx.y;
    const int b    = blockIdx.z;
    const int R0   = 20 * band - 1;                      // first band source row
    const int Y0   = 80 * band;

    // load source band (smem row r holds global row clamp(R0 + r))
    const float* Sg = g_S + ((size_t)(b * D_ + d)) * HW_;
    for (int i = threadIdx.x; i < SRCROWS * 40; i += 256) {
        const int r  = i / 40;
        const int x4 = i % 40;
        const int gr = min(max(R0 + r, 0), H_ - 1);
        *reinterpret_cast<float4*>(&sS[r * 160 + x4 * 4]) =
            *reinterpret_cast<const float4*>(Sg + gr * 160 + x4 * 4);
    }
    __syncthreads();

    const int w    = threadIdx.x >> 5;
    const int lane = threadIdx.x & 31;
    float* wstage = smem + BAND_FLOATS + w * (2 * ROW_FLOATS);
    const char* gbase = (const char*)(out + ((size_t)(b * D_ + d)) * (OH_ * OW_));

    for (int ri = 0; ri < 10; ri++) {
        const int y   = Y0 + w + 8 * ri;
        const int buf = ri & 1;
        float* srow = wstage + buf * ROW_FLOATS;

        // before overwriting this buffer, ensure TMA finished READING it
        if (ri >= 2) {
            if (lane == 0)
                asm volatile("cp.async.bulk.wait_group.read 1;" ::: "memory");
        }
        __syncwarp();

        const int yy = y - 2;
        const int g  = (yy >= 0) ? (yy >> 2) : -1;
        const int k  = yy - 4 * g;
        const float fy = 0.125f + 0.25f * (float)k;

        const float* row0 = &sS[(min(max(g, 0), H_ - 1) - R0) * 160];
        const float* row1 = &sS[(min(g + 1,     H_ - 1) - R0) * 160];

        #pragma unroll
        for (int j = 0; j < 5; j++) {
            const int c  = 32 * j + lane;
            const int cm = max(c - 1, 0);
            const int cp = min(c + 1, W_ - 1);

            const float a0 = row0[cm], a1 = row0[c], a2 = row0[cp];
            const float b0 = row1[cm], b1 = row1[c], b2 = row1[cp];
            const float v0 = fmaf(fy, b0 - a0, a0);
            const float v1 = fmaf(fy, b1 - a1, a1);
            const float v2 = fmaf(fy, b2 - a2, a2);
            const float da = v1 - v0;
            const float db = v2 - v1;

            float4 o;
            o.x = (fmaf(0.625f, da, v0) > 0.5f) ? 1.0f : 0.0f;
            o.y = (fmaf(0.875f, da, v0) > 0.5f) ? 1.0f : 0.0f;
            o.z = (fmaf(0.125f, db, v1) > 0.5f) ? 1.0f : 0.0f;
            o.w = (fmaf(0.375f, db, v1) > 0.5f) ? 1.0f : 0.0f;
            *reinterpret_cast<float4*>(srow + 4 * c) = o;
        }

        // make STS visible to the async proxy, then one lane issues the copy
        asm volatile("fence.proxy.async.shared::cta;" ::: "memory");
        __syncwarp();
        if (lane == 0) {
            const uint32_t s32 = (uint32_t)__cvta_generic_to_shared(srow);
            asm volatile("cp.async.bulk.global.shared::cta.bulk_group [%0], [%1], %2;"
                         :: "l"(gbase + (size_t)y * (OW_ * 4)),
                            "r"(s32), "r"((uint32_t)(ROW_FLOATS * 4))
                         : "memory");
            asm volatile("cp.async.bulk.commit_group;" ::: "memory");
        }
    }

    // full completion before kernel end
    if (lane == 0)
        asm volatile("cp.async.bulk.wait_group 0;" ::: "memory");
}

// ---------------------------------------------------------------------------
extern "C" void kernel_launch(void* const* d_in, const int* in_sizes, int n_in,
                              void* d_out, int out_size)
{
    // Size-based binding (robust to order/units): det << mc < proto
    const float* mc    = nullptr;
    const float* proto = nullptr;
    const void*  det   = nullptr;

    for (int i = 0; i < n_in; i++) {
        const long long s = in_sizes[i];
        if      (s == 1075200LL || s == 4300800LL)                        mc    = (const float*)d_in[i];
        else if (s == 3276800LL || s == 13107200LL)                       proto = (const float*)d_in[i];
        else if (s == 400LL || s == 800LL || s == 1600LL || s == 3200LL)  det   = d_in[i];
    }
    if (!mc || !proto || !det) {
        int imin = 0, imax = 0;
        for (int i = 1; i < 3 && i < n_in; i++) {
            if (in_sizes[i] < in_sizes[imin]) imin = i;
            if (in_sizes[i] > in_sizes[imax]) imax = i;
        }
        const int imid = 3 - imin - imax;
        det   = d_in[imin];
        proto = (const float*)d_in[imax];
        mc    = (const float*)d_in[imid];
    }

    float* out = (float*)d_out;     // [4,100,640,640] f32 (0.0/1.0)
    (void)out_size;

    cudaFuncSetAttribute(kernelB, cudaFuncAttributeMaxDynamicSharedMemorySize, SMEMB_BYTES);

    // 4-chunk d-pipeline: A_i on null stream; B_i on HIGH-PRIORITY stream s
    // after evA_i, so B CTAs win work-distributor slots over queued A blocks.
    // Objects created fresh each call (deterministic); intentionally not
    // destroyed (destroy mid-capture illegal; harness calls this only a few
    // times).
    int prLo = 0, prHi = 0;
    cudaDeviceGetStreamPriorityRange(&prLo, &prHi);      // prHi = highest
    cudaStream_t s;
    cudaStreamCreateWithPriority(&s, cudaStreamNonBlocking, prHi);

    cudaEvent_t evA[4], evB;
    for (int i = 0; i < 4; i++) cudaEventCreateWithFlags(&evA[i], cudaEventDisableTiming);
    cudaEventCreateWithFlags(&evB, cudaEventDisableTiming);

    for (int i = 0; i < 4; i++) {
        kernelA<<<dim3(HW_ / (256 * PXT_), 25 / DT_, B_), 256>>>(mc, proto, det, 25 * i);
        cudaEventRecord(evA[i], 0);
    }
    for (int i = 0; i < 4; i++) {
        cudaStreamWaitEvent(s, evA[i], 0);
        kernelB<<<dim3(8, 25, B_), 256, SMEMB_BYTES, s>>>(out, 25 * i);
    }
    cudaEventRecord(evB, s);
    cudaStreamWaitEvent(0, evB, 0);
}

// round 14
// speedup vs baseline: 1.0921x; 1.0921x over previous
#include <cuda_runtime.h>
#include <math.h>
#include <stdint.h>

// Problem constants
#define B_   4
#define N_   8400
#define NM_  32
#define H_   160
#define W_   160
#define D_   100
#define HW_  (H_*W_)          // 25600
#define OW_  640
#define OH_  640

// Scratch: sigmoid masks [B][D][H][W] fp32 = 40.96 MB
__device__ float g_S[(size_t)B_ * D_ * HW_];

// Packed fp32x2 FMA (Blackwell FFMA2) — PTX-only
__device__ __forceinline__ float2 ffma2(float2 a, float2 b, float2 c) {
    union { float2 f; unsigned long long u; } ua, ub, uc, ur;
    ua.f = a; ub.f = b; uc.f = c;
    asm("fma.rn.f32x2 %0, %1, %2, %3;" : "=l"(ur.u) : "l"(ua.u), "l"(ub.u), "l"(uc.u));
    return ur.f;
}

// ---------------------------------------------------------------------------
// Kernel A (one-pass): thread = one pixel, ALL 100 d.
// Proto pixel (32 ch) in registers, loaded once; coeffs [100][32] in smem.
// grid (200, 4); block 128 -> 800 blocks = one wave at ~5.4 CTAs/SM.
// ---------------------------------------------------------------------------
#define ABLK 128

__global__ void __launch_bounds__(ABLK)
kernelA(const float* __restrict__ mc,
        const float* __restrict__ proto,
        const void* __restrict__ det)      // int32 vs int64 detected on device
{
    const int b  = blockIdx.y;
    const int p0 = blockIdx.x * ABLK + threadIdx.x;

    __shared__ float sc[D_ * NM_];         // coeffs [d][ch], 12.8 KB

    // int64 det values < 2^31 -> all odd int32 words zero
    const int* d32 = (const int*)det;
    bool is64 = true;
    #pragma unroll
    for (int k = 0; k < 8; k++) if (d32[2 * k + 1] != 0) is64 = false;

    // coeff gather: one float4 (4 channels) per item
    for (int i = threadIdx.x; i < D_ * 8; i += ABLK) {
        const int d = i >> 3;
        const int q = i & 7;
        long long idx = is64 ? ((const long long*)det)[b * D_ + d]
                             : (long long)d32[b * D_ + d];
        idx = min(max(idx, 0LL), (long long)(N_ - 1));
        *reinterpret_cast<float4*>(&sc[d * NM_ + 4 * q]) =
            *reinterpret_cast<const float4*>(mc + ((long long)b * N_ + idx) * NM_ + 4 * q);
    }

    // proto pixel -> 16 channel-pair registers (read once per channel plane)
    float2 pr[NM_ / 2];
    {
        const float* src = proto + (size_t)b * NM_ * HW_ + p0;
        #pragma unroll
        for (int k = 0; k < NM_ / 2; k++) {
            pr[k].x = src[(size_t)(2 * k)     * HW_];
            pr[k].y = src[(size_t)(2 * k + 1) * HW_];
        }
    }
    __syncthreads();

    float* gs = g_S + (size_t)b * D_ * HW_ + p0;

    #pragma unroll 2
    for (int d = 0; d < D_; d++) {
        const float4* cq = reinterpret_cast<const float4*>(&sc[d * NM_]);
        float2 a0 = make_float2(0.f, 0.f);
        float2 a1 = make_float2(0.f, 0.f);
        #pragma unroll
        for (int q = 0; q < 8; q++) {
            const float4 c = cq[q];
            a0 = ffma2(make_float2(c.x, c.y), pr[2 * q],     a0);
            a1 = ffma2(make_float2(c.z, c.w), pr[2 * q + 1], a1);
        }
        const float s = (a0.x + a0.y) + (a1.x + a1.y);
        gs[(size_t)d * HW_] = 1.0f / (1.0f + __expf(-s));
    }
}

// ---------------------------------------------------------------------------
// Kernel B (R9 design, unchanged): 4x bilinear upsample + threshold; per-warp
// row pipelines with per-row TMA bulk stores (double-buffered, wait read 1).
// grid (8 bands, 100 d, 4 b); block 256 (8 warps); smem 55 KB -> 4 CTAs/SM.
// ---------------------------------------------------------------------------
#define SRCROWS      22                                  // 20 + 2 halo
#define BAND_FLOATS  (SRCROWS * 160)                     // 3520 floats
#define ROW_FLOATS   OW_                                 // 640 floats = 2560 B
#define SMEMB_BYTES  ((BAND_FLOATS + 8 * 2 * ROW_FLOATS) * 4)   // 55040 B

__global__ void __launch_bounds__(256)
kernelB(float* __restrict__ out)
{
    extern __shared__ float smem[];
    float* sS = smem;                                    // [22][160] band

    const int band = blockIdx.x;                         // 0..7
    const int d    = blockIdx.y;
    const int b    = blockIdx.z;
    const int R0   = 20 * band - 1;                      // first band source row
    const int Y0   = 80 * band;

    // load source band (smem row r holds global row clamp(R0 + r))
    const float* Sg = g_S + ((size_t)(b * D_ + d)) * HW_;
    for (int i = threadIdx.x; i < SRCROWS * 40; i += 256) {
        const int r  = i / 40;
        const int x4 = i % 40;
        const int gr = min(max(R0 + r, 0), H_ - 1);
        *reinterpret_cast<float4*>(&sS[r * 160 + x4 * 4]) =
            *reinterpret_cast<const float4*>(Sg + gr * 160 + x4 * 4);
    }
    __syncthreads();

    const int w    = threadIdx.x >> 5;
    const int lane = threadIdx.x & 31;
    float* wstage = smem + BAND_FLOATS + w * (2 * ROW_FLOATS);
    const char* gbase = (const char*)(out + ((size_t)(b * D_ + d)) * (OH_ * OW_));

    for (int ri = 0; ri < 10; ri++) {
        const int y   = Y0 + w + 8 * ri;
        const int buf = ri & 1;
        float* srow = wstage + buf * ROW_FLOATS;

        // before overwriting this buffer, ensure TMA finished READING it
        if (ri >= 2) {
            if (lane == 0)
                asm volatile("cp.async.bulk.wait_group.read 1;" ::: "memory");
        }
        __syncwarp();

        const int yy = y - 2;
        const int g  = (yy >= 0) ? (yy >> 2) : -1;
        const int k  = yy - 4 * g;
        const float fy = 0.125f + 0.25f * (float)k;

        const float* row0 = &sS[(min(max(g, 0), H_ - 1) - R0) * 160];
        const float* row1 = &sS[(min(g + 1,     H_ - 1) - R0) * 160];

        #pragma unroll
        for (int j = 0; j < 5; j++) {
            const int c  = 32 * j + lane;
            const int cm = max(c - 1, 0);
            const int cp = min(c + 1, W_ - 1);

            const float a0 = row0[cm], a1 = row0[c], a2 = row0[cp];
            const float b0 = row1[cm], b1 = row1[c], b2 = row1[cp];
            const float v0 = fmaf(fy, b0 - a0, a0);
            const float v1 = fmaf(fy, b1 - a1, a1);
            const float v2 = fmaf(fy, b2 - a2, a2);
            const float da = v1 - v0;
            const float db = v2 - v1;

            float4 o;
            o.x = (fmaf(0.625f, da, v0) > 0.5f) ? 1.0f : 0.0f;
            o.y = (fmaf(0.875f, da, v0) > 0.5f) ? 1.0f : 0.0f;
            o.z = (fmaf(0.125f, db, v1) > 0.5f) ? 1.0f : 0.0f;
            o.w = (fmaf(0.375f, db, v1) > 0.5f) ? 1.0f : 0.0f;
            *reinterpret_cast<float4*>(srow + 4 * c) = o;
        }

        // make STS visible to the async proxy, then one lane issues the copy
        asm volatile("fence.proxy.async.shared::cta;" ::: "memory");
        __syncwarp();
        if (lane == 0) {
            const uint32_t s32 = (uint32_t)__cvta_generic_to_shared(srow);
            asm volatile("cp.async.bulk.global.shared::cta.bulk_group [%0], [%1], %2;"
                         :: "l"(gbase + (size_t)y * (OW_ * 4)),
                            "r"(s32), "r"((uint32_t)(ROW_FLOATS * 4))
                         : "memory");
            asm volatile("cp.async.bulk.commit_group;" ::: "memory");
        }
    }

    // full completion before kernel end
    if (lane == 0)
        asm volatile("cp.async.bulk.wait_group 0;" ::: "memory");
}

// ---------------------------------------------------------------------------
extern "C" void kernel_launch(void* const* d_in, const int* in_sizes, int n_in,
                              void* d_out, int out_size)
{
    // Size-based binding (robust to order/units): det << mc < proto
    const float* mc    = nullptr;
    const float* proto = nullptr;
    const void*  det   = nullptr;

    for (int i = 0; i < n_in; i++) {
        const long long s = in_sizes[i];
        if      (s == 1075200LL || s == 4300800LL)                        mc    = (const float*)d_in[i];
        else if (s == 3276800LL || s == 13107200LL)                       proto = (const float*)d_in[i];
        else if (s == 400LL || s == 800LL || s == 1600LL || s == 3200LL)  det   = d_in[i];
    }
    if (!mc || !proto || !det) {
        int imin = 0, imax = 0;
        for (int i = 1; i < 3 && i < n_in; i++) {
            if (in_sizes[i] < in_sizes[imin]) imin = i;
            if (in_sizes[i] > in_sizes[imax]) imax = i;
        }
        const int imid = 3 - imin - imax;
        det   = d_in[imin];
        proto = (const float*)d_in[imax];
        mc    = (const float*)d_in[imid];
    }

    float* out = (float*)d_out;     // [4,100,640,640] f32 (0.0/1.0)
    (void)out_size;

    cudaFuncSetAttribute(kernelB, cudaFuncAttributeMaxDynamicSharedMemorySize, SMEMB_BYTES);

    // Serial: one efficient A (proto read once), then B at full tilt.
    kernelA<<<dim3(HW_ / ABLK, B_), ABLK>>>(mc, proto, det);
    kernelB<<<dim3(8, D_, B_), 256, SMEMB_BYTES>>>(out);
}